// round 4
// baseline (speedup 1.0000x reference)
#include <cuda_runtime.h>
#include <math.h>

#define NN 4
#define C1 128
#define C2 36
#define Hh 192
#define Ww 192
#define HO 190
#define WO 190
#define HW (Hh*Ww)
#define HWO (HO*WO)

typedef unsigned long long ull;

// Scratch (device globals: allocation-free rule)
__device__ float  g_offset[NN*C2*HWO];     // offset conv output [N,36,HO,WO]
__device__ float  g_wt[9*C1*C2];           // deform_w [tap][c][o], BN-scaled
__device__ float  g_bias[C2];              // folded BN bias
__device__ float4 g_xt[(size_t)NN*HW*32];  // x transposed to NHWC [N,H,W,C]

// ---- packed f32x2 helpers -------------------------------------------------
__device__ __forceinline__ ull fma2(ull a, ull b, ull c) {
    ull d; asm("fma.rn.f32x2 %0,%1,%2,%3;" : "=l"(d) : "l"(a), "l"(b), "l"(c));
    return d;
}
__device__ __forceinline__ ull mul2(ull a, ull b) {
    ull d; asm("mul.rn.f32x2 %0,%1,%2;" : "=l"(d) : "l"(a), "l"(b));
    return d;
}
__device__ __forceinline__ ull add2(ull a, ull b) {
    ull d; asm("add.rn.f32x2 %0,%1,%2;" : "=l"(d) : "l"(a), "l"(b));
    return d;
}
__device__ __forceinline__ ull pack2(float x, float y) {
    ull d; asm("mov.b64 %0,{%1,%2};" : "=l"(d) : "f"(x), "f"(y));
    return d;
}
__device__ __forceinline__ float lo2(ull a) { return __uint_as_float((unsigned)a); }
__device__ __forceinline__ float hi2(ull a) { return __uint_as_float((unsigned)(a >> 32)); }

// ---------------------------------------------------------------------------
// Prep: transpose deform_w [o][c][3][3] -> g_wt[tap][c][o], folding BN scale.
// ---------------------------------------------------------------------------
__global__ void prep_kernel(const float* __restrict__ dw,
                            const float* __restrict__ gamma,
                            const float* __restrict__ beta,
                            const float* __restrict__ mean,
                            const float* __restrict__ var)
{
    int idx = blockIdx.x * 256 + threadIdx.x;
    if (idx < 9 * C1 * C2) {
        int t = idx / (C1 * C2);
        int r = idx % (C1 * C2);
        int c = r / C2, o = r % C2;
        float s = gamma[o] * rsqrtf(var[o] + 1e-5f);
        g_wt[idx] = dw[(o * C1 + c) * 9 + t] * s;
    }
    if (idx < C2) {
        float s = gamma[idx] * rsqrtf(var[idx] + 1e-5f);
        g_bias[idx] = beta[idx] - mean[idx] * s;
    }
}

// ---------------------------------------------------------------------------
// Transpose x [N,C,H,W] -> g_xt [N,H,W,C]  (32x32 smem tile)
// ---------------------------------------------------------------------------
__global__ __launch_bounds__(256) void transpose_kernel(const float* __restrict__ x)
{
    __shared__ float sx[32][33];
    int n  = blockIdx.z >> 2;
    int ct = (blockIdx.z & 3) * 32;
    int y  = blockIdx.y;
    int w0 = blockIdx.x * 32;
    int tid = threadIdx.x;
    int col = tid & 31, rw = tid >> 5;

    const float* xb = x + ((size_t)n * C1 + ct) * HW + y * Ww + w0;
#pragma unroll
    for (int i = 0; i < 4; i++) {
        int c = rw + i * 8;
        sx[c][col] = xb[(size_t)c * HW + col];
    }
    __syncthreads();

    float* ob = (float*)g_xt + ((size_t)n * HW + y * Ww + w0) * 128 + ct;
#pragma unroll
    for (int i = 0; i < 4; i++) {
        int wl = rw + i * 8;
        ob[(size_t)wl * 128 + col] = sx[col][wl];
    }
}

// ---------------------------------------------------------------------------
// Offset-generating grouped conv (groups=4, VALID, 3x3) — round-1 version.
// ---------------------------------------------------------------------------
__global__ __launch_bounds__(192) void offset_conv_kernel(
    const float* __restrict__ x, const float* __restrict__ cw)
{
    __shared__ float sx[32 * 8 * 34];
    __shared__ float ws[32 * 9 * 9];

    int n = blockIdx.z >> 2;
    int g = blockIdx.z & 3;
    int x0 = blockIdx.x * 32;
    int y0 = blockIdx.y * 6;
    int tid = threadIdx.x;

    for (int idx = tid; idx < 2592; idx += 192) {
        int o = idx % 9; int rem = idx / 9;
        int tap = rem % 9; int ci = rem / 9;
        ws[idx] = cw[((g * 9 + o) * 32 + ci) * 9 + tap];
    }

    const float* xb = x + ((size_t)n * C1 + g * 32) * HW;
    for (int idx = tid; idx < 32 * 8 * 34; idx += 192) {
        int ci = idx / 272;
        int r  = (idx % 272) / 34;
        int col = idx % 34;
        int gy = y0 + r, gx = x0 + col;
        float v = 0.f;
        if (gy < Hh && gx < Ww) v = xb[ci * HW + gy * Ww + gx];
        sx[idx] = v;
    }
    __syncthreads();

    int lx = tid & 31, ly = tid >> 5;
    float acc[9];
#pragma unroll
    for (int o = 0; o < 9; o++) acc[o] = 0.f;

    for (int ci = 0; ci < 32; ci++) {
        int base = ci * 272 + ly * 34 + lx;
#pragma unroll
        for (int tap = 0; tap < 9; tap++) {
            int i = tap / 3, j = tap % 3;
            float v = sx[base + i * 34 + j];
            const float* wp = &ws[(ci * 9 + tap) * 9];
#pragma unroll
            for (int o = 0; o < 9; o++) acc[o] = fmaf(v, wp[o], acc[o]);
        }
    }

    int yy = y0 + ly, xx = x0 + lx;
    if (yy < HO && xx < WO) {
        float* op = g_offset + ((size_t)n * C2 + g * 9) * HWO + yy * WO + xx;
#pragma unroll
        for (int o = 0; o < 9; o++) op[o * HWO] = acc[o];
    }
}

// ---------------------------------------------------------------------------
// Deformable conv + folded BN + Mish.
// Warp = 8 pixels x 4 lanes; each lane owns 16 channels per dg-half,
// gathers them as LDG.128 from NHWC, FFMA2 GEMM vs per-tap smem weights,
// butterfly-reduce partial sums over the quad.
// ---------------------------------------------------------------------------
__global__ __launch_bounds__(256, 2) void deform_kernel(float* __restrict__ out)
{
    __shared__ float wts[C1 * C2];   // current tap weights [128c][36o] = 18KB

    int n = blockIdx.y;
    int tid = threadIdx.x;
    int q = tid & 3;
    int p = blockIdx.x * 64 + (tid >> 2);
    bool act = (p < HWO);
    int pcl = act ? p : (HWO - 1);
    int yy = pcl / WO, xx = pcl % WO;

    const float* xt = (const float*)g_xt + (size_t)n * HW * 128;
    const float* offb = g_offset + (size_t)n * C2 * HWO + pcl;

    ull acc[18];
#pragma unroll
    for (int j = 0; j < 18; j++) acc[j] = 0ull;

    for (int t = 0; t < 9; t++) {
        __syncthreads();
        {   // stage tap weights: 4608 floats = 1152 float4
            const float4* gw = (const float4*)(g_wt + t * C1 * C2);
            float4* wd = (float4*)wts;
#pragma unroll
            for (int i = 0; i < 4; i++) wd[tid + i * 256] = gw[tid + i * 256];
            if (tid < 128) wd[tid + 1024] = gw[tid + 1024];
        }
        __syncthreads();

        int ti = t / 3, tj = t % 3;
#pragma unroll
        for (int dg = 0; dg < 2; dg++) {
            float dy = offb[(dg * 18 + t * 2    ) * HWO];
            float dx = offb[(dg * 18 + t * 2 + 1) * HWO];
            float py = (float)(yy + ti) + dy;
            float px = (float)(xx + tj) + dx;
            float fy0 = floorf(py), fx0 = floorf(px);
            float wy1 = py - fy0, wx1 = px - fx0;
            float wy0 = 1.f - wy1, wx0 = 1.f - wx1;
            bool vy0 = (fy0       >= 0.f) && (fy0       <= (float)(Hh - 1));
            bool vy1 = (fy0 + 1.f >= 0.f) && (fy0 + 1.f <= (float)(Hh - 1));
            bool vx0 = (fx0       >= 0.f) && (fx0       <= (float)(Ww - 1));
            bool vx1 = (fx0 + 1.f >= 0.f) && (fx0 + 1.f <= (float)(Ww - 1));
            int y0i = (int)fy0, x0i = (int)fx0;
            int y0c = min(max(y0i,     0), Hh - 1);
            int y1c = min(max(y0i + 1, 0), Hh - 1);
            int x0c = min(max(x0i,     0), Ww - 1);
            int x1c = min(max(x0i + 1, 0), Ww - 1);
            float W00 = wy0 * wx0 * ((vy0 && vx0) ? 1.f : 0.f);
            float W01 = wy0 * wx1 * ((vy0 && vx1) ? 1.f : 0.f);
            float W10 = wy1 * wx0 * ((vy1 && vx0) ? 1.f : 0.f);
            float W11 = wy1 * wx1 * ((vy1 && vx1) ? 1.f : 0.f);
            int o00 = y0c * Ww + x0c, o01 = y0c * Ww + x1c;
            int o10 = y1c * Ww + x0c, o11 = y1c * Ww + x1c;

            ull W00_2 = pack2(W00, W00), W01_2 = pack2(W01, W01);
            ull W10_2 = pack2(W10, W10), W11_2 = pack2(W11, W11);

            int cb = dg * 64 + q * 16;
            const ulonglong2* b00 = (const ulonglong2*)(xt + (size_t)o00 * 128 + cb);
            const ulonglong2* b01 = (const ulonglong2*)(xt + (size_t)o01 * 128 + cb);
            const ulonglong2* b10 = (const ulonglong2*)(xt + (size_t)o10 * 128 + cb);
            const ulonglong2* b11 = (const ulonglong2*)(xt + (size_t)o11 * 128 + cb);
            const float* wbase = wts + cb * C2;

#pragma unroll
            for (int iter = 0; iter < 4; iter++) {
                ulonglong2 c00 = b00[iter], c01 = b01[iter];
                ulonglong2 c10 = b10[iter], c11 = b11[iter];
                ull vab = fma2(W00_2, c00.x, fma2(W01_2, c01.x,
                          fma2(W10_2, c10.x, mul2(W11_2, c11.x))));
                ull vcd = fma2(W00_2, c00.y, fma2(W01_2, c01.y,
                          fma2(W10_2, c10.y, mul2(W11_2, c11.y))));
                float v0 = lo2(vab), v1 = hi2(vab);
                float v2 = lo2(vcd), v3 = hi2(vcd);
                const ulonglong2* wr =
                    (const ulonglong2*)(wbase + iter * 4 * C2);
#pragma unroll
                for (int k = 0; k < 4; k++) {
                    float vk = (k == 0) ? v0 : (k == 1) ? v1 : (k == 2) ? v2 : v3;
                    ull vv = pack2(vk, vk);
                    const ulonglong2* w = wr + k * 9;
#pragma unroll
                    for (int j = 0; j < 9; j++) {
                        ulonglong2 ww = w[j];
                        acc[2 * j]     = fma2(vv, ww.x, acc[2 * j]);
                        acc[2 * j + 1] = fma2(vv, ww.y, acc[2 * j + 1]);
                    }
                }
            }
        }
    }

    // reduce partial sums over the 4-lane quad (butterfly -> all lanes have sum)
#pragma unroll
    for (int j = 0; j < 18; j++) {
        acc[j] = add2(acc[j], __shfl_xor_sync(0xffffffffu, acc[j], 1));
        acc[j] = add2(acc[j], __shfl_xor_sync(0xffffffffu, acc[j], 2));
    }

    if (act) {
        float* ob = out + (size_t)n * C2 * HWO + p;
#pragma unroll
        for (int pr = 0; pr < 18; pr++) {
            int wl = (pr * 4) / 18;      // compile-time writer lane per pair
            if (q == wl) {
                int o0 = 2 * pr;
                float z0 = lo2(acc[pr]) + __ldg(g_bias + o0);
                float z1 = hi2(acc[pr]) + __ldg(g_bias + o0 + 1);
                float sp0 = (z0 > 20.f) ? z0 : log1pf(expf(z0));
                float sp1 = (z1 > 20.f) ? z1 : log1pf(expf(z1));
                ob[(size_t)o0 * HWO]       = z0 * tanhf(sp0);
                ob[(size_t)(o0 + 1) * HWO] = z1 * tanhf(sp1);
            }
        }
    }
}

// ---------------------------------------------------------------------------
extern "C" void kernel_launch(void* const* d_in, const int* in_sizes, int n_in,
                              void* d_out, int out_size)
{
    const float* x        = (const float*)d_in[0];
    const float* conv_w   = (const float*)d_in[1];
    const float* deform_w = (const float*)d_in[2];
    const float* bn_gamma = (const float*)d_in[3];
    const float* bn_beta  = (const float*)d_in[4];
    const float* bn_mean  = (const float*)d_in[5];
    const float* bn_var   = (const float*)d_in[6];
    float* out = (float*)d_out;

    prep_kernel<<<(9 * C1 * C2 + 255) / 256, 256>>>(
        deform_w, bn_gamma, bn_beta, bn_mean, bn_var);

    transpose_kernel<<<dim3(6, 192, 16), 256>>>(x);

    offset_conv_kernel<<<dim3(6, 32, 16), 192>>>(x, conv_w);

    deform_kernel<<<dim3((HWO + 63) / 64, NN), 256>>>(out);
}

// round 5
// speedup vs baseline: 3.7022x; 3.7022x over previous
#include <cuda_runtime.h>
#include <math.h>

#define NN 4
#define C1 128
#define C2 36
#define Hh 192
#define Ww 192
#define HO 190
#define WO 190
#define HW (Hh*Ww)
#define HWO (HO*WO)

typedef unsigned long long ull;

// Scratch (device globals: allocation-free rule)
__device__ float g_offset[NN*C2*HWO];   // offset conv output [N,36,HO,WO]
__device__ float g_wt[9*C1*C2];         // deform_w [tap][c][o], BN-scaled
__device__ float g_bias[C2];            // folded BN bias

// ---- packed f32x2 helpers -------------------------------------------------
__device__ __forceinline__ ull fma2(ull a, ull b, ull c) {
    ull d; asm("fma.rn.f32x2 %0,%1,%2,%3;" : "=l"(d) : "l"(a), "l"(b), "l"(c));
    return d;
}
__device__ __forceinline__ ull pack2(float x, float y) {
    ull d; asm("mov.b64 %0,{%1,%2};" : "=l"(d) : "f"(x), "f"(y));
    return d;
}
__device__ __forceinline__ float lo2(ull a) { return __uint_as_float((unsigned)a); }
__device__ __forceinline__ float hi2(ull a) { return __uint_as_float((unsigned)(a >> 32)); }

// ---------------------------------------------------------------------------
// Prep: transpose deform_w [o][c][3][3] -> g_wt[tap][c][o], folding BN scale.
// ---------------------------------------------------------------------------
__global__ void prep_kernel(const float* __restrict__ dw,
                            const float* __restrict__ gamma,
                            const float* __restrict__ beta,
                            const float* __restrict__ mean,
                            const float* __restrict__ var)
{
    int idx = blockIdx.x * 256 + threadIdx.x;
    if (idx < 9 * C1 * C2) {
        int t = idx / (C1 * C2);
        int r = idx % (C1 * C2);
        int c = r / C2, o = r % C2;
        float s = gamma[o] * rsqrtf(var[o] + 1e-5f);
        g_wt[idx] = dw[(o * C1 + c) * 9 + t] * s;
    }
    if (idx < C2) {
        float s = gamma[idx] * rsqrtf(var[idx] + 1e-5f);
        g_bias[idx] = beta[idx] - mean[idx] * s;
    }
}

// ---------------------------------------------------------------------------
// Offset-generating grouped conv (groups=4, VALID, 3x3) — round-1 version.
// ---------------------------------------------------------------------------
__global__ __launch_bounds__(192) void offset_conv_kernel(
    const float* __restrict__ x, const float* __restrict__ cw)
{
    __shared__ float sx[32 * 8 * 34];
    __shared__ float ws[32 * 9 * 9];

    int n = blockIdx.z >> 2;
    int g = blockIdx.z & 3;
    int x0 = blockIdx.x * 32;
    int y0 = blockIdx.y * 6;
    int tid = threadIdx.x;

    for (int idx = tid; idx < 2592; idx += 192) {
        int o = idx % 9; int rem = idx / 9;
        int tap = rem % 9; int ci = rem / 9;
        ws[idx] = cw[((g * 9 + o) * 32 + ci) * 9 + tap];
    }

    const float* xb = x + ((size_t)n * C1 + g * 32) * HW;
    for (int idx = tid; idx < 32 * 8 * 34; idx += 192) {
        int ci = idx / 272;
        int r  = (idx % 272) / 34;
        int col = idx % 34;
        int gy = y0 + r, gx = x0 + col;
        float v = 0.f;
        if (gy < Hh && gx < Ww) v = xb[ci * HW + gy * Ww + gx];
        sx[idx] = v;
    }
    __syncthreads();

    int lx = tid & 31, ly = tid >> 5;
    float acc[9];
#pragma unroll
    for (int o = 0; o < 9; o++) acc[o] = 0.f;

    for (int ci = 0; ci < 32; ci++) {
        int base = ci * 272 + ly * 34 + lx;
#pragma unroll
        for (int tap = 0; tap < 9; tap++) {
            int i = tap / 3, j = tap % 3;
            float v = sx[base + i * 34 + j];
            const float* wp = &ws[(ci * 9 + tap) * 9];
#pragma unroll
            for (int o = 0; o < 9; o++) acc[o] = fmaf(v, wp[o], acc[o]);
        }
    }

    int yy = y0 + ly, xx = x0 + lx;
    if (yy < HO && xx < WO) {
        float* op = g_offset + ((size_t)n * C2 + g * 9) * HWO + yy * WO + xx;
#pragma unroll
        for (int o = 0; o < 9; o++) op[o * HWO] = acc[o];
    }
}

// ---------------------------------------------------------------------------
// Deformable conv + folded BN + Mish — round-1 structure + FFMA2 accumulate.
// One thread per output pixel; 18 packed f32x2 accumulators; per-tap weights
// staged in smem as [c][36] and read as broadcast ulonglong2 (LDS.128).
// ---------------------------------------------------------------------------
__global__ __launch_bounds__(128, 4) void deform_kernel(
    const float* __restrict__ x, float* __restrict__ out)
{
    __shared__ float wts[C1 * C2];   // per-tap weights [c=128][o=36] = 18KB

    int n = blockIdx.y;
    int p = blockIdx.x * 128 + threadIdx.x;
    bool active = (p < HWO);
    if (!active) p = HWO - 1;
    int yy = p / WO, xx = p % WO;

    const float* xb = x + (size_t)n * C1 * HW;
    const float* offb = g_offset + (size_t)n * C2 * HWO + yy * WO + xx;
    const float4* gwt4 = (const float4*)g_wt;

    ull acc[18];
#pragma unroll
    for (int j = 0; j < 18; j++) acc[j] = 0ull;

    for (int t = 0; t < 9; t++) {
        __syncthreads();
        {
            float4* wd = (float4*)wts;
            const float4* gw = gwt4 + t * 1152;
#pragma unroll
            for (int i = 0; i < 9; i++)
                wd[threadIdx.x + i * 128] = gw[threadIdx.x + i * 128];
        }
        __syncthreads();

        int i = t / 3, j = t % 3;
#pragma unroll
        for (int dg = 0; dg < 2; dg++) {
            float dy = offb[(dg * 18 + t * 2    ) * HWO];
            float dx = offb[(dg * 18 + t * 2 + 1) * HWO];
            float py = (float)(yy + i) + dy;
            float px = (float)(xx + j) + dx;
            float fy0 = floorf(py), fx0 = floorf(px);
            float wy1 = py - fy0, wx1 = px - fx0;
            float wy0 = 1.f - wy1, wx0 = 1.f - wx1;

            bool vy0 = (fy0       >= 0.f) && (fy0       <= (float)(Hh - 1));
            bool vy1 = (fy0 + 1.f >= 0.f) && (fy0 + 1.f <= (float)(Hh - 1));
            bool vx0 = (fx0       >= 0.f) && (fx0       <= (float)(Ww - 1));
            bool vx1 = (fx0 + 1.f >= 0.f) && (fx0 + 1.f <= (float)(Ww - 1));

            int y0i = (int)fy0, x0i = (int)fx0;
            int y0c = min(max(y0i,     0), Hh - 1);
            int y1c = min(max(y0i + 1, 0), Hh - 1);
            int x0c = min(max(x0i,     0), Ww - 1);
            int x1c = min(max(x0i + 1, 0), Ww - 1);

            float W00 = wy0 * wx0 * ((vy0 && vx0) ? 1.f : 0.f);
            float W01 = wy0 * wx1 * ((vy0 && vx1) ? 1.f : 0.f);
            float W10 = wy1 * wx0 * ((vy1 && vx0) ? 1.f : 0.f);
            float W11 = wy1 * wx1 * ((vy1 && vx1) ? 1.f : 0.f);

            int o00 = y0c * Ww + x0c, o01 = y0c * Ww + x1c;
            int o10 = y1c * Ww + x0c, o11 = y1c * Ww + x1c;

            const float* pc = xb + dg * 64 * HW;
            const ulonglong2* wb = (const ulonglong2*)(wts + dg * 64 * C2);

#pragma unroll 2
            for (int c = 0; c < 64; c++) {
                const float* pp = pc + c * HW;
                float v = fmaf(W00, __ldg(pp + o00),
                          fmaf(W01, __ldg(pp + o01),
                          fmaf(W10, __ldg(pp + o10),
                               W11 * __ldg(pp + o11))));
                ull vv = pack2(v, v);
                const ulonglong2* wp = wb + c * 9;   // 36 floats = 9 x 16B
#pragma unroll
                for (int q = 0; q < 9; q++) {
                    ulonglong2 ww = wp[q];
                    acc[2 * q]     = fma2(vv, ww.x, acc[2 * q]);
                    acc[2 * q + 1] = fma2(vv, ww.y, acc[2 * q + 1]);
                }
            }
        }
    }

    if (active) {
        float* ob = out + (size_t)n * C2 * HWO + yy * WO + xx;
#pragma unroll
        for (int pr = 0; pr < 18; pr++) {
            int o0 = 2 * pr;
            float z0 = lo2(acc[pr]) + __ldg(g_bias + o0);
            float z1 = hi2(acc[pr]) + __ldg(g_bias + o0 + 1);
            float sp0 = (z0 > 20.f) ? z0 : log1pf(expf(z0));
            float sp1 = (z1 > 20.f) ? z1 : log1pf(expf(z1));
            ob[(size_t)o0 * HWO]       = z0 * tanhf(sp0);
            ob[(size_t)(o0 + 1) * HWO] = z1 * tanhf(sp1);
        }
    }
}

// ---------------------------------------------------------------------------
extern "C" void kernel_launch(void* const* d_in, const int* in_sizes, int n_in,
                              void* d_out, int out_size)
{
    const float* x        = (const float*)d_in[0];
    const float* conv_w   = (const float*)d_in[1];
    const float* deform_w = (const float*)d_in[2];
    const float* bn_gamma = (const float*)d_in[3];
    const float* bn_beta  = (const float*)d_in[4];
    const float* bn_mean  = (const float*)d_in[5];
    const float* bn_var   = (const float*)d_in[6];
    float* out = (float*)d_out;

    prep_kernel<<<(9 * C1 * C2 + 255) / 256, 256>>>(
        deform_w, bn_gamma, bn_beta, bn_mean, bn_var);

    offset_conv_kernel<<<dim3(6, 32, 16), 192>>>(x, conv_w);

    deform_kernel<<<dim3((HWO + 127) / 128, NN), 128>>>(x, out);
}

// round 6
// speedup vs baseline: 3.8393x; 1.0370x over previous
#include <cuda_runtime.h>
#include <math.h>

#define NN 4
#define C1 128
#define C2 36
#define Hh 192
#define Ww 192
#define HO 190
#define WO 190
#define HW (Hh*Ww)
#define HWO (HO*WO)

typedef unsigned long long ull;

// Scratch (device globals: allocation-free rule)
__device__ float g_offset[NN*C2*HWO];   // offset conv output [N,36,HO,WO]
__device__ float g_wt[9*C1*C2];         // deform_w [tap][c][o], BN-scaled
__device__ float g_bias[C2];            // folded BN bias

// ---- packed f32x2 helpers -------------------------------------------------
__device__ __forceinline__ ull fma2(ull a, ull b, ull c) {
    ull d; asm("fma.rn.f32x2 %0,%1,%2,%3;" : "=l"(d) : "l"(a), "l"(b), "l"(c));
    return d;
}
__device__ __forceinline__ ull pack2(float x, float y) {
    ull d; asm("mov.b64 %0,{%1,%2};" : "=l"(d) : "f"(x), "f"(y));
    return d;
}
__device__ __forceinline__ float lo2(ull a) { return __uint_as_float((unsigned)a); }
__device__ __forceinline__ float hi2(ull a) { return __uint_as_float((unsigned)(a >> 32)); }

// ---------------------------------------------------------------------------
// Prep: transpose deform_w [o][c][3][3] -> g_wt[tap][c][o], folding BN scale.
// ---------------------------------------------------------------------------
__global__ void prep_kernel(const float* __restrict__ dw,
                            const float* __restrict__ gamma,
                            const float* __restrict__ beta,
                            const float* __restrict__ mean,
                            const float* __restrict__ var)
{
    int idx = blockIdx.x * 256 + threadIdx.x;
    if (idx < 9 * C1 * C2) {
        int t = idx / (C1 * C2);
        int r = idx % (C1 * C2);
        int c = r / C2, o = r % C2;
        float s = gamma[o] * rsqrtf(var[o] + 1e-5f);
        g_wt[idx] = dw[(o * C1 + c) * 9 + t] * s;
    }
    if (idx < C2) {
        float s = gamma[idx] * rsqrtf(var[idx] + 1e-5f);
        g_bias[idx] = beta[idx] - mean[idx] * s;
    }
}

// ---------------------------------------------------------------------------
// Offset-generating grouped conv (groups=4, VALID, 3x3) — round-1 version.
// ---------------------------------------------------------------------------
__global__ __launch_bounds__(192) void offset_conv_kernel(
    const float* __restrict__ x, const float* __restrict__ cw)
{
    __shared__ float sx[32 * 8 * 34];
    __shared__ float ws[32 * 9 * 9];

    int n = blockIdx.z >> 2;
    int g = blockIdx.z & 3;
    int x0 = blockIdx.x * 32;
    int y0 = blockIdx.y * 6;
    int tid = threadIdx.x;

    for (int idx = tid; idx < 2592; idx += 192) {
        int o = idx % 9; int rem = idx / 9;
        int tap = rem % 9; int ci = rem / 9;
        ws[idx] = cw[((g * 9 + o) * 32 + ci) * 9 + tap];
    }

    const float* xb = x + ((size_t)n * C1 + g * 32) * HW;
    for (int idx = tid; idx < 32 * 8 * 34; idx += 192) {
        int ci = idx / 272;
        int r  = (idx % 272) / 34;
        int col = idx % 34;
        int gy = y0 + r, gx = x0 + col;
        float v = 0.f;
        if (gy < Hh && gx < Ww) v = xb[ci * HW + gy * Ww + gx];
        sx[idx] = v;
    }
    __syncthreads();

    int lx = tid & 31, ly = tid >> 5;
    float acc[9];
#pragma unroll
    for (int o = 0; o < 9; o++) acc[o] = 0.f;

    for (int ci = 0; ci < 32; ci++) {
        int base = ci * 272 + ly * 34 + lx;
#pragma unroll
        for (int tap = 0; tap < 9; tap++) {
            int i = tap / 3, j = tap % 3;
            float v = sx[base + i * 34 + j];
            const float* wp = &ws[(ci * 9 + tap) * 9];
#pragma unroll
            for (int o = 0; o < 9; o++) acc[o] = fmaf(v, wp[o], acc[o]);
        }
    }

    int yy = y0 + ly, xx = x0 + lx;
    if (yy < HO && xx < WO) {
        float* op = g_offset + ((size_t)n * C2 + g * 9) * HWO + yy * WO + xx;
#pragma unroll
        for (int o = 0; o < 9; o++) op[o * HWO] = acc[o];
    }
}

// ---------------------------------------------------------------------------
// Bilinear context
// ---------------------------------------------------------------------------
struct Ctx {
    int o00, o01, o10, o11;
    float W00, W01, W10, W11;
};

__device__ __forceinline__ Ctx make_ctx(int yy, int xx, int i, int j,
                                        float dy, float dx)
{
    Ctx c;
    float py = (float)(yy + i) + dy;
    float px = (float)(xx + j) + dx;
    float fy0 = floorf(py), fx0 = floorf(px);
    float wy1 = py - fy0, wx1 = px - fx0;
    float wy0 = 1.f - wy1, wx0 = 1.f - wx1;

    bool vy0 = (fy0       >= 0.f) && (fy0       <= (float)(Hh - 1));
    bool vy1 = (fy0 + 1.f >= 0.f) && (fy0 + 1.f <= (float)(Hh - 1));
    bool vx0 = (fx0       >= 0.f) && (fx0       <= (float)(Ww - 1));
    bool vx1 = (fx0 + 1.f >= 0.f) && (fx0 + 1.f <= (float)(Ww - 1));

    int y0i = (int)fy0, x0i = (int)fx0;
    int y0c = min(max(y0i,     0), Hh - 1);
    int y1c = min(max(y0i + 1, 0), Hh - 1);
    int x0c = min(max(x0i,     0), Ww - 1);
    int x1c = min(max(x0i + 1, 0), Ww - 1);

    c.W00 = wy0 * wx0 * ((vy0 && vx0) ? 1.f : 0.f);
    c.W01 = wy0 * wx1 * ((vy0 && vx1) ? 1.f : 0.f);
    c.W10 = wy1 * wx0 * ((vy1 && vx0) ? 1.f : 0.f);
    c.W11 = wy1 * wx1 * ((vy1 && vx1) ? 1.f : 0.f);

    c.o00 = y0c * Ww + x0c; c.o01 = y0c * Ww + x1c;
    c.o10 = y1c * Ww + x0c; c.o11 = y1c * Ww + x1c;
    return c;
}

// ---------------------------------------------------------------------------
// Deformable conv + folded BN + Mish.
// One thread per output pixel. Per tap: both dg contexts live, merged c-loop
// issues 8 independent gathers per iteration (unroll 4 -> ptxas front-batches
// up to 32 LDGs) to hide L2 latency. FFMA2 accumulate, broadcast LDS weights.
// ---------------------------------------------------------------------------
__global__ __launch_bounds__(128, 4) void deform_kernel(
    const float* __restrict__ x, float* __restrict__ out)
{
    __shared__ float wts[C1 * C2];   // per-tap weights [c=128][o=36] = 18KB

    int n = blockIdx.y;
    int p = blockIdx.x * 128 + threadIdx.x;
    bool active = (p < HWO);
    if (!active) p = HWO - 1;
    int yy = p / WO, xx = p % WO;

    const float* xb = x + (size_t)n * C1 * HW;
    const float* offb = g_offset + (size_t)n * C2 * HWO + yy * WO + xx;
    const float4* gwt4 = (const float4*)g_wt;

    ull acc[18];
#pragma unroll
    for (int j = 0; j < 18; j++) acc[j] = 0ull;

    for (int t = 0; t < 9; t++) {
        __syncthreads();
        {
            float4* wd = (float4*)wts;
            const float4* gw = gwt4 + t * 1152;
#pragma unroll
            for (int i = 0; i < 9; i++)
                wd[threadIdx.x + i * 128] = gw[threadIdx.x + i * 128];
        }
        __syncthreads();

        int ti = t / 3, tj = t % 3;

        float dy0 = offb[(t * 2     ) * HWO];
        float dx0 = offb[(t * 2 + 1 ) * HWO];
        float dy1 = offb[(18 + t * 2) * HWO];
        float dx1 = offb[(19 + t * 2) * HWO];
        Ctx A = make_ctx(yy, xx, ti, tj, dy0, dx0);
        Ctx B = make_ctx(yy, xx, ti, tj, dy1, dx1);

        const float* x0p = xb;             // dg0 channels 0..63
        const float* x1p = xb + 64 * HW;   // dg1 channels 64..127
        const ulonglong2* w0 = (const ulonglong2*)wts;             // [c][36]
        const ulonglong2* w1 = (const ulonglong2*)(wts + 64 * C2);

#pragma unroll 4
        for (int c = 0; c < 64; c++) {
            const float* p0 = x0p + c * HW;
            const float* p1 = x1p + c * HW;
            float a00 = __ldg(p0 + A.o00), a01 = __ldg(p0 + A.o01);
            float a10 = __ldg(p0 + A.o10), a11 = __ldg(p0 + A.o11);
            float b00 = __ldg(p1 + B.o00), b01 = __ldg(p1 + B.o01);
            float b10 = __ldg(p1 + B.o10), b11 = __ldg(p1 + B.o11);

            float v0 = fmaf(A.W00, a00, fmaf(A.W01, a01,
                       fmaf(A.W10, a10, A.W11 * a11)));
            float v1 = fmaf(B.W00, b00, fmaf(B.W01, b01,
                       fmaf(B.W10, b10, B.W11 * b11)));
            ull vv0 = pack2(v0, v0);
            ull vv1 = pack2(v1, v1);

            const ulonglong2* wp0 = w0 + c * 9;
            const ulonglong2* wp1 = w1 + c * 9;
#pragma unroll
            for (int q = 0; q < 9; q++) {
                ulonglong2 ww0 = wp0[q];
                ulonglong2 ww1 = wp1[q];
                acc[2 * q]     = fma2(vv0, ww0.x, acc[2 * q]);
                acc[2 * q + 1] = fma2(vv0, ww0.y, acc[2 * q + 1]);
                acc[2 * q]     = fma2(vv1, ww1.x, acc[2 * q]);
                acc[2 * q + 1] = fma2(vv1, ww1.y, acc[2 * q + 1]);
            }
        }
    }

    if (active) {
        float* ob = out + (size_t)n * C2 * HWO + yy * WO + xx;
#pragma unroll
        for (int pr = 0; pr < 18; pr++) {
            int o0 = 2 * pr;
            float z0 = lo2(acc[pr]) + __ldg(g_bias + o0);
            float z1 = hi2(acc[pr]) + __ldg(g_bias + o0 + 1);
            float sp0 = (z0 > 20.f) ? z0 : log1pf(expf(z0));
            float sp1 = (z1 > 20.f) ? z1 : log1pf(expf(z1));
            ob[(size_t)o0 * HWO]       = z0 * tanhf(sp0);
            ob[(size_t)(o0 + 1) * HWO] = z1 * tanhf(sp1);
        }
    }
}

// ---------------------------------------------------------------------------
extern "C" void kernel_launch(void* const* d_in, const int* in_sizes, int n_in,
                              void* d_out, int out_size)
{
    const float* x        = (const float*)d_in[0];
    const float* conv_w   = (const float*)d_in[1];
    const float* deform_w = (const float*)d_in[2];
    const float* bn_gamma = (const float*)d_in[3];
    const float* bn_beta  = (const float*)d_in[4];
    const float* bn_mean  = (const float*)d_in[5];
    const float* bn_var   = (const float*)d_in[6];
    float* out = (float*)d_out;

    prep_kernel<<<(9 * C1 * C2 + 255) / 256, 256>>>(
        deform_w, bn_gamma, bn_beta, bn_mean, bn_var);

    offset_conv_kernel<<<dim3(6, 32, 16), 192>>>(x, conv_w);

    deform_kernel<<<dim3((HWO + 127) / 128, NN), 128>>>(x, out);
}